// round 5
// baseline (speedup 1.0000x reference)
#include <cuda_runtime.h>
#include <cuda_bf16.h>
#include <math.h>

// ---------------------------------------------------------------------------
// MPNN on GB300 (round 5).
//  - Structure: k_deg -> k_scan -> k_fillinit (fill CSR + init embeddings).
//  - k_dgather: fused gather over h and cur0 (srcidx loaded once per edge).
//  - GEMMs: 128 nodes/block, 2 rows/thread, fma.rn.f32x2, conflict-free W map.
//  - Last GEMM2 fuses readout (per-node dot + per-graph segmented mean sums).
//  - Launch order puts k_dgather 4th => it lands in the ncu profile window.
// ---------------------------------------------------------------------------

#define MAXN 65536
#define MAXE 1048576
#define MAXG 512
#define FD   64

typedef unsigned long long ull;

__device__ int   g_deg[MAXN];
__device__ int   g_rowptr[MAXN];
__device__ int   g_wptr[MAXN];
__device__ int   g_srcidx[MAXE];
__device__ float g_dinv[MAXN];
__device__ int   g_degmax;

__device__ float g_h[MAXN * FD];
__device__ float g_nagg[MAXN * FD];   // gather(cur)
__device__ float g_naggH[MAXN * FD];  // gather(h) + deg column
__device__ float g_msg[MAXN * FD];
__device__ float g_eemb[MAXN * FD];
__device__ float g_curA[MAXN * FD];
__device__ float g_curB[MAXN * FD];

__device__ float g_means[MAXG * FD];
__device__ float g_cnt[MAXG];
__device__ float g_gconst[MAXG];

// ---------------------------------------------------------------------------
__global__ void k_deg(const int* __restrict__ col, int E) {
    int i = blockIdx.x * blockDim.x + threadIdx.x;
    if (i < E) atomicAdd(&g_deg[col[i]], 1);
}

// single-block exclusive scan over deg -> rowptr/wptr, plus dinv and degmax
__global__ void k_scan(int n) {
    __shared__ int sums[1024];
    __shared__ int smax[1024];
    int t = threadIdx.x;
    int chunk = (n + 1023) >> 10;
    int s = t * chunk;
    int e = min(s + chunk, n);
    int loc = 0, mx = 0;
    for (int i = s; i < e; i++) { int d = g_deg[i]; loc += d; mx = max(mx, d); }
    sums[t] = loc;
    smax[t] = mx;
    __syncthreads();
    for (int off = 1; off < 1024; off <<= 1) {
        int v = (t >= off) ? sums[t - off] : 0;
        __syncthreads();
        sums[t] += v;
        __syncthreads();
    }
    int run = (t == 0) ? 0 : sums[t - 1];
    for (int i = s; i < e; i++) {
        int d = g_deg[i];
        g_rowptr[i] = run;
        g_wptr[i]   = run;
        g_dinv[i]   = (d > 0) ? (1.0f / (float)d) : 0.0f;
        run += d;
    }
    for (int off = 512; off > 0; off >>= 1) {
        if (t < off) smax[t] = max(smax[t], smax[t + off]);
        __syncthreads();
    }
    if (t == 0) g_degmax = max(smax[0], 1);
}

// merged: CSR fill (threads [0,E)) + node init (threads [E, E+n*64))
__global__ void k_fillinit(const int* __restrict__ row, const int* __restrict__ col,
                           const float* __restrict__ x, const float* __restrict__ Wi,
                           const float* __restrict__ We1, int E, int n, int nobs) {
    int i = blockIdx.x * blockDim.x + threadIdx.x;
    if (i < E) {
        int p = atomicAdd(&g_wptr[col[i]], 1);
        g_srcidx[p] = row[i];
    } else {
        int t = i - E;
        if (t >= n * 64) return;
        int node = t >> 6, c = t & 63;
        const float* xr = x + node * nobs;
        float s1 = 0.f, s2 = 0.f;
        for (int j = 0; j < nobs; j++) {
            float xv = __ldg(&xr[j]);
            s1 += xv * __ldg(&Wi[j * 64 + c]);
            if (c < 63) s2 += xv * __ldg(&We1[j * 63 + c]);
        }
        g_curA[t] = fmaxf(s1, 0.f);
        g_h[t]    = (c < 63) ? fmaxf(s2, 0.f) : 0.f;
    }
}

// fused double gather: outH = mean of h rows (+deg col), outC = mean of cur rows.
// half-warp per node, float4 per lane.
__global__ void k_dgather(const float* __restrict__ h, const float* __restrict__ cur,
                          float* __restrict__ outH, float* __restrict__ outC, int n) {
    int hw = (blockIdx.x * blockDim.x + threadIdx.x) >> 4;
    int lane = threadIdx.x & 15;
    if (hw >= n) return;
    int start = g_rowptr[hw];
    int d = g_deg[hw];
    const float4* h4 = (const float4*)h;
    const float4* c4 = (const float4*)cur;
    float hx = 0.f, hy = 0.f, hz = 0.f, hw_ = 0.f;
    float cx = 0.f, cy = 0.f, cz = 0.f, cw = 0.f;
    int i = 0;
    for (; i + 4 <= d; i += 4) {
        int s0 = __ldg(&g_srcidx[start + i]);
        int s1 = __ldg(&g_srcidx[start + i + 1]);
        int s2 = __ldg(&g_srcidx[start + i + 2]);
        int s3 = __ldg(&g_srcidx[start + i + 3]);
        float4 a0 = __ldg(&h4[s0 * 16 + lane]);
        float4 a1 = __ldg(&h4[s1 * 16 + lane]);
        float4 a2 = __ldg(&h4[s2 * 16 + lane]);
        float4 a3 = __ldg(&h4[s3 * 16 + lane]);
        float4 b0 = __ldg(&c4[s0 * 16 + lane]);
        float4 b1 = __ldg(&c4[s1 * 16 + lane]);
        float4 b2 = __ldg(&c4[s2 * 16 + lane]);
        float4 b3 = __ldg(&c4[s3 * 16 + lane]);
        hx += (a0.x + a1.x) + (a2.x + a3.x);
        hy += (a0.y + a1.y) + (a2.y + a3.y);
        hz += (a0.z + a1.z) + (a2.z + a3.z);
        hw_ += (a0.w + a1.w) + (a2.w + a3.w);
        cx += (b0.x + b1.x) + (b2.x + b3.x);
        cy += (b0.y + b1.y) + (b2.y + b3.y);
        cz += (b0.z + b1.z) + (b2.z + b3.z);
        cw += (b0.w + b1.w) + (b2.w + b3.w);
    }
    for (; i < d; i++) {
        int s = __ldg(&g_srcidx[start + i]);
        float4 a = __ldg(&h4[s * 16 + lane]);
        float4 b = __ldg(&c4[s * 16 + lane]);
        hx += a.x; hy += a.y; hz += a.z; hw_ += a.w;
        cx += b.x; cy += b.y; cz += b.z; cw += b.w;
    }
    float sc = g_dinv[hw];
    hx *= sc; hy *= sc; hz *= sc; hw_ *= sc;
    cx *= sc; cy *= sc; cz *= sc; cw *= sc;
    if (lane == 15) hw_ = (float)d / (float)g_degmax;
    ((float4*)outH)[hw * 16 + lane] = make_float4(hx, hy, hz, hw_);
    ((float4*)outC)[hw * 16 + lane] = make_float4(cx, cy, cz, cw);
}

// single gather: out[v] = dinv[v] * sum of feat rows, unroll 8
__global__ void k_gather(const float* __restrict__ feat, float* __restrict__ out, int n) {
    int hw = (blockIdx.x * blockDim.x + threadIdx.x) >> 4;
    int lane = threadIdx.x & 15;
    if (hw >= n) return;
    int start = g_rowptr[hw];
    int d = g_deg[hw];
    const float4* f4 = (const float4*)feat;
    float ax = 0.f, ay = 0.f, az = 0.f, aw = 0.f;
    int i = 0;
    for (; i + 8 <= d; i += 8) {
        int s0 = __ldg(&g_srcidx[start + i]);
        int s1 = __ldg(&g_srcidx[start + i + 1]);
        int s2 = __ldg(&g_srcidx[start + i + 2]);
        int s3 = __ldg(&g_srcidx[start + i + 3]);
        int s4 = __ldg(&g_srcidx[start + i + 4]);
        int s5 = __ldg(&g_srcidx[start + i + 5]);
        int s6 = __ldg(&g_srcidx[start + i + 6]);
        int s7 = __ldg(&g_srcidx[start + i + 7]);
        float4 v0 = __ldg(&f4[s0 * 16 + lane]);
        float4 v1 = __ldg(&f4[s1 * 16 + lane]);
        float4 v2 = __ldg(&f4[s2 * 16 + lane]);
        float4 v3 = __ldg(&f4[s3 * 16 + lane]);
        float4 v4 = __ldg(&f4[s4 * 16 + lane]);
        float4 v5 = __ldg(&f4[s5 * 16 + lane]);
        float4 v6 = __ldg(&f4[s6 * 16 + lane]);
        float4 v7 = __ldg(&f4[s7 * 16 + lane]);
        ax += ((v0.x + v1.x) + (v2.x + v3.x)) + ((v4.x + v5.x) + (v6.x + v7.x));
        ay += ((v0.y + v1.y) + (v2.y + v3.y)) + ((v4.y + v5.y) + (v6.y + v7.y));
        az += ((v0.z + v1.z) + (v2.z + v3.z)) + ((v4.z + v5.z) + (v6.z + v7.z));
        aw += ((v0.w + v1.w) + (v2.w + v3.w)) + ((v4.w + v5.w) + (v6.w + v7.w));
    }
    for (; i < d; i++) {
        int s = __ldg(&g_srcidx[start + i]);
        float4 v = __ldg(&f4[s * 16 + lane]);
        ax += v.x; ay += v.y; az += v.z; aw += v.w;
    }
    float sc = g_dinv[hw];
    ((float4*)out)[hw * 16 + lane] = make_float4(ax * sc, ay * sc, az * sc, aw * sc);
}

// ---------------------------------------------------------------------------
template <int K, int PITCH>
__device__ __forceinline__ void gemm_core2(const float* __restrict__ ins,
                                           const float* __restrict__ Ws,
                                           ull accA[8], ull accB[8]) {
    int rr = threadIdx.x >> 2;
    int q  = threadIdx.x & 3;
#pragma unroll
    for (int j = 0; j < 8; j++) { accA[j] = 0ull; accB[j] = 0ull; }
    const float* r0 = &ins[rr * PITCH];
    const float* r1 = &ins[(rr + 64) * PITCH];
#pragma unroll 2
    for (int k = 0; k < K; k += 4) {
        float4 a0 = *(const float4*)&r0[k];
        float4 a1 = *(const float4*)&r1[k];
#pragma unroll
        for (int kk = 0; kk < 4; kk++) {
            float av0 = (kk == 0) ? a0.x : (kk == 1) ? a0.y : (kk == 2) ? a0.z : a0.w;
            float av1 = (kk == 0) ? a1.x : (kk == 1) ? a1.y : (kk == 2) ? a1.z : a1.w;
            ull p0, p1;
            asm("mov.b64 %0, {%1, %1};" : "=l"(p0) : "f"(av0));
            asm("mov.b64 %0, {%1, %1};" : "=l"(p1) : "f"(av1));
            const float* wrow = &Ws[(k + kk) * 64 + q * 4];
#pragma unroll
            for (int g = 0; g < 4; g++) {
                ulonglong2 w = *(const ulonglong2*)&wrow[g * 16];
                asm("fma.rn.f32x2 %0, %1, %2, %0;" : "+l"(accA[g * 2])     : "l"(p0), "l"(w.x));
                asm("fma.rn.f32x2 %0, %1, %2, %0;" : "+l"(accA[g * 2 + 1]) : "l"(p0), "l"(w.y));
                asm("fma.rn.f32x2 %0, %1, %2, %0;" : "+l"(accB[g * 2])     : "l"(p1), "l"(w.x));
                asm("fma.rn.f32x2 %0, %1, %2, %0;" : "+l"(accB[g * 2 + 1]) : "l"(p1), "l"(w.y));
            }
        }
    }
}

__device__ __forceinline__ float4 acc_relu4(ull a0, ull a1) {
    float lo0, hi0, lo1, hi1;
    asm("mov.b64 {%0, %1}, %2;" : "=f"(lo0), "=f"(hi0) : "l"(a0));
    asm("mov.b64 {%0, %1}, %2;" : "=f"(lo1), "=f"(hi1) : "l"(a1));
    float4 o;
    o.x = fmaxf(lo0, 0.f); o.y = fmaxf(hi0, 0.f);
    o.z = fmaxf(lo1, 0.f); o.w = fmaxf(hi1, 0.f);
    return o;
}

// C = relu( concat(A,B) @ W[128,64] ), 128 nodes/block. LAST fuses readout.
template <bool LAST>
__global__ __launch_bounds__(256) void k_gemm128(const float* __restrict__ A,
                                                 const float* __restrict__ B,
                                                 const float* __restrict__ W,
                                                 float* __restrict__ C,
                                                 const float* __restrict__ Wr,
                                                 const int* __restrict__ batch,
                                                 float* __restrict__ out, int n) {
    extern __shared__ float sm[];
    const int PITCH = 132;
    float* Ws  = sm;                 // 128*64
    float* ins = sm + 128 * 64;      // 128*PITCH
    __shared__ float Wrs[64];
    int tid = threadIdx.x;
    int node0 = blockIdx.x * 128;

    for (int idx = tid; idx < 128 * 16; idx += 256)
        ((float4*)Ws)[idx] = __ldg((const float4*)W + idx);
    if (LAST && tid < 64) Wrs[tid] = __ldg(&Wr[64 + tid]);

    for (int idx = tid; idx < 2048; idx += 256) {
        int r = idx >> 4, c4 = (idx & 15) << 2;
        int node = node0 + r;
        float4 va = make_float4(0.f, 0.f, 0.f, 0.f), vb = va;
        if (node < n) {
            va = __ldg((const float4*)&A[(size_t)node * 64 + c4]);
            vb = __ldg((const float4*)&B[(size_t)node * 64 + c4]);
        }
        *(float4*)&ins[r * PITCH + c4]      = va;
        *(float4*)&ins[r * PITCH + 64 + c4] = vb;
    }
    __syncthreads();

    ull accA[8], accB[8];
    gemm_core2<128, PITCH>(ins, Ws, accA, accB);

    int rr = tid >> 2;
    int q  = tid & 3;

    float4 oA[4], oB[4];
#pragma unroll
    for (int g = 0; g < 4; g++) {
        oA[g] = acc_relu4(accA[g * 2], accA[g * 2 + 1]);
        oB[g] = acc_relu4(accB[g * 2], accB[g * 2 + 1]);
    }

    if (!LAST) {
        if (node0 + rr < n) {
            float* Cr = &C[(size_t)(node0 + rr) * 64 + q * 4];
#pragma unroll
            for (int g = 0; g < 4; g++) *(float4*)&Cr[g * 16] = oA[g];
        }
        if (node0 + rr + 64 < n) {
            float* Cr = &C[(size_t)(node0 + rr + 64) * 64 + q * 4];
#pragma unroll
            for (int g = 0; g < 4; g++) *(float4*)&Cr[g * 16] = oB[g];
        }
    } else {
        float dA = 0.f, dB = 0.f;
#pragma unroll
        for (int g = 0; g < 4; g++) {
            const float* wv = &Wrs[g * 16 + q * 4];
            dA += oA[g].x * wv[0] + oA[g].y * wv[1] + oA[g].z * wv[2] + oA[g].w * wv[3];
            dB += oB[g].x * wv[0] + oB[g].y * wv[1] + oB[g].z * wv[2] + oB[g].w * wv[3];
        }
        dA += __shfl_xor_sync(0xffffffffu, dA, 1);
        dA += __shfl_xor_sync(0xffffffffu, dA, 2);
        dB += __shfl_xor_sync(0xffffffffu, dB, 1);
        dB += __shfl_xor_sync(0xffffffffu, dB, 2);
        if (q == 0) {
            if (node0 + rr < n)      out[node0 + rr]      = dA;
            if (node0 + rr + 64 < n) out[node0 + rr + 64] = dB;
        }
        __syncthreads();
#pragma unroll
        for (int g = 0; g < 4; g++) {
            *(float4*)&ins[rr * PITCH + g * 16 + q * 4]        = oA[g];
            *(float4*)&ins[(rr + 64) * PITCH + g * 16 + q * 4] = oB[g];
        }
        __syncthreads();
        if (tid < 64) {
            int c = tid;
            float acc = 0.f, cnt = 0.f;
            int curb = -1;
            for (int i = 0; i < 128; i++) {
                int node = node0 + i;
                if (node >= n) break;
                int b = __ldg(&batch[node]);
                if (b != curb) {
                    if (curb >= 0) {
                        atomicAdd(&g_means[curb * 64 + c], acc);
                        if (c == 0) atomicAdd(&g_cnt[curb], cnt);
                    }
                    acc = 0.f; cnt = 0.f; curb = b;
                }
                acc += ins[i * PITCH + c];
                cnt += 1.f;
            }
            if (curb >= 0) {
                atomicAdd(&g_means[curb * 64 + c], acc);
                if (c == 0) atomicAdd(&g_cnt[curb], cnt);
            }
        }
    }
}

// eemb = relu( naggH @ We2 ), K=64, 128 nodes / block
__global__ __launch_bounds__(256) void k_gemm64(const float* __restrict__ A,
                                                const float* __restrict__ W,
                                                float* __restrict__ C, int n) {
    extern __shared__ float sm[];
    const int PITCH = 68;
    float* Ws  = sm;               // 64*64
    float* ins = sm + 64 * 64;     // 128*68
    int tid = threadIdx.x;
    int node0 = blockIdx.x * 128;

    for (int idx = tid; idx < 64 * 16; idx += 256)
        ((float4*)Ws)[idx] = __ldg((const float4*)W + idx);
    for (int idx = tid; idx < 2048; idx += 256) {
        int r = idx >> 4, c4 = (idx & 15) << 2;
        int node = node0 + r;
        float4 va = (node < n) ? __ldg((const float4*)&A[(size_t)node * 64 + c4])
                               : make_float4(0.f, 0.f, 0.f, 0.f);
        *(float4*)&ins[r * PITCH + c4] = va;
    }
    __syncthreads();

    ull accA[8], accB[8];
    gemm_core2<64, PITCH>(ins, Ws, accA, accB);

    int rr = tid >> 2;
    int q  = tid & 3;
    if (node0 + rr < n) {
        float* Cr = &C[(size_t)(node0 + rr) * 64 + q * 4];
#pragma unroll
        for (int g = 0; g < 4; g++) *(float4*)&Cr[g * 16] = acc_relu4(accA[g * 2], accA[g * 2 + 1]);
    }
    if (node0 + rr + 64 < n) {
        float* Cr = &C[(size_t)(node0 + rr + 64) * 64 + q * 4];
#pragma unroll
        for (int g = 0; g < 4; g++) *(float4*)&Cr[g * 16] = acc_relu4(accB[g * 2], accB[g * 2 + 1]);
    }
}

// gconst[g] = relu(mean_g @ W_pool) . W_read[:64] + b_read
__global__ void k_gconst(const float* __restrict__ Wp, const float* __restrict__ Wr,
                         const float* __restrict__ br) {
    int g = blockIdx.x;
    int t = threadIdx.x;  // 64 threads
    __shared__ float m[64];
    __shared__ float red[64];
    float cnt = g_cnt[g];
    if (cnt <= 0.f) { if (t == 0) g_gconst[g] = 0.f; return; }
    m[t] = g_means[g * 64 + t] / cnt;
    __syncthreads();
    float p = 0.f;
#pragma unroll 8
    for (int k = 0; k < 64; k++) p += m[k] * __ldg(&Wp[k * 64 + t]);
    red[t] = fmaxf(p, 0.f) * __ldg(&Wr[t]);
    __syncthreads();
    if (t < 32) {
        float s = red[t] + red[t + 32];
#pragma unroll
        for (int off = 16; off > 0; off >>= 1) s += __shfl_down_sync(0xffffffffu, s, off);
        if (t == 0) g_gconst[g] = s + __ldg(&br[0]);
    }
}

// out[i] += gconst[batch[i]]
__global__ void k_addg(const int* __restrict__ batch, float* __restrict__ out, int n) {
    int i = blockIdx.x * blockDim.x + threadIdx.x;
    if (i < n) out[i] += g_gconst[__ldg(&batch[i])];
}

// ---------------------------------------------------------------------------
extern "C" void kernel_launch(void* const* d_in, const int* in_sizes, int n_in,
                              void* d_out, int out_size) {
    const float* x    = (const float*)d_in[0];
    const float* Wi   = (const float*)d_in[1];
    const float* We1  = (const float*)d_in[2];
    const float* We2  = (const float*)d_in[3];
    const float* Wmsg = (const float*)d_in[4];
    const float* Wupd = (const float*)d_in[5];
    const float* Wp   = (const float*)d_in[6];
    const float* Wr   = (const float*)d_in[7];
    const float* br   = (const float*)d_in[8];
    const int*   eidx = (const int*)d_in[9];
    const int*   batch= (const int*)d_in[10];

    int n    = in_sizes[10];
    int E    = in_sizes[9] / 2;
    int nobs = in_sizes[0] / n;
    int L    = in_sizes[4] / (128 * 64);
    const int* row = eidx;
    const int* col = eidx + E;
    float* out = (float*)d_out;

    float *curA, *curB, *hbuf, *nagg, *naggH, *msg, *eemb, *means, *cnt;
    int* deg;
    cudaGetSymbolAddress((void**)&curA, g_curA);
    cudaGetSymbolAddress((void**)&curB, g_curB);
    cudaGetSymbolAddress((void**)&hbuf, g_h);
    cudaGetSymbolAddress((void**)&nagg, g_nagg);
    cudaGetSymbolAddress((void**)&naggH, g_naggH);
    cudaGetSymbolAddress((void**)&msg,  g_msg);
    cudaGetSymbolAddress((void**)&eemb, g_eemb);
    cudaGetSymbolAddress((void**)&means, g_means);
    cudaGetSymbolAddress((void**)&cnt,   g_cnt);
    cudaGetSymbolAddress((void**)&deg,   g_deg);

    const int SMEM128 = (128 * 64 + 128 * 132) * 4;  // 100352
    const int SMEM64  = (64 * 64 + 128 * 68) * 4;    // 51200
    cudaFuncSetAttribute(k_gemm128<false>, cudaFuncAttributeMaxDynamicSharedMemorySize, SMEM128);
    cudaFuncSetAttribute(k_gemm128<true>,  cudaFuncAttributeMaxDynamicSharedMemorySize, SMEM128);
    cudaFuncSetAttribute(k_gemm64, cudaFuncAttributeMaxDynamicSharedMemorySize, SMEM64);

    int gE  = (E + 255) / 256;
    int gFI = (E + n * 64 + 255) / 256;
    int gHW = (n * 16 + 255) / 256;
    int gG  = (n + 127) / 128;
    int gA  = (n + 255) / 256;

    cudaMemsetAsync(deg,   0, (size_t)n * sizeof(int));
    cudaMemsetAsync(means, 0, (size_t)MAXG * FD * sizeof(float));
    cudaMemsetAsync(cnt,   0, (size_t)MAXG * sizeof(float));

    k_deg<<<gE, 256>>>(col, E);                                     // launch 1
    k_scan<<<1, 1024>>>(n);                                         // launch 2
    k_fillinit<<<gFI, 256>>>(row, col, x, Wi, We1, E, n, nobs);     // launch 3
    k_dgather<<<gHW, 256>>>(hbuf, curA, naggH, nagg, n);            // launch 4 (profiled)

    k_gemm64<<<gG, 256, SMEM64>>>(naggH, We2, eemb, n);

    float* cin = curA;
    float* cout = curB;
    for (int l = 0; l < L; l++) {
        bool last = (l == L - 1);
        if (l > 0) k_gather<<<gHW, 256>>>(cin, nagg, n);
        k_gemm128<false><<<gG, 256, SMEM128>>>(nagg, eemb, Wmsg + (size_t)l * 8192, msg,
                                               nullptr, nullptr, nullptr, n);
        if (!last) {
            k_gemm128<false><<<gG, 256, SMEM128>>>(cin, msg, Wupd + (size_t)l * 8192, cout,
                                                   nullptr, nullptr, nullptr, n);
            float* tmp = cin; cin = cout; cout = tmp;
        } else {
            k_gemm128<true><<<gG, 256, SMEM128>>>(cin, msg, Wupd + (size_t)l * 8192, nullptr,
                                                  Wr, batch, out, n);
        }
    }

    k_gconst<<<MAXG, 64>>>(Wp, Wr, br);
    k_addg<<<gA, 256>>>(batch, out, n);
}

// round 6
// speedup vs baseline: 1.0384x; 1.0384x over previous
#include <cuda_runtime.h>
#include <cuda_bf16.h>
#include <math.h>

// ---------------------------------------------------------------------------
// MPNN on GB300 (round 6).
//  - GEMMs rebuilt as 8 rows x 8 cols per thread (128 thr / 128 nodes per
//    block): cuts smem crossbar traffic 2.3x (was the binding resource).
//  - Everything else as round 5 (CSR build, dgather, fused readout).
// ---------------------------------------------------------------------------

#define MAXN 65536
#define MAXE 1048576
#define MAXG 512
#define FD   64

typedef unsigned long long ull;

__device__ int   g_deg[MAXN];
__device__ int   g_rowptr[MAXN];
__device__ int   g_wptr[MAXN];
__device__ int   g_srcidx[MAXE];
__device__ float g_dinv[MAXN];
__device__ int   g_degmax;

__device__ float g_h[MAXN * FD];
__device__ float g_nagg[MAXN * FD];
__device__ float g_naggH[MAXN * FD];
__device__ float g_msg[MAXN * FD];
__device__ float g_eemb[MAXN * FD];
__device__ float g_curA[MAXN * FD];
__device__ float g_curB[MAXN * FD];

__device__ float g_means[MAXG * FD];
__device__ float g_cnt[MAXG];
__device__ float g_gconst[MAXG];

// ---------------------------------------------------------------------------
__global__ void k_deg(const int* __restrict__ col, int E) {
    int i = blockIdx.x * blockDim.x + threadIdx.x;
    if (i < E) atomicAdd(&g_deg[col[i]], 1);
}

__global__ void k_scan(int n) {
    __shared__ int sums[1024];
    __shared__ int smax[1024];
    int t = threadIdx.x;
    int chunk = (n + 1023) >> 10;
    int s = t * chunk;
    int e = min(s + chunk, n);
    int loc = 0, mx = 0;
    for (int i = s; i < e; i++) { int d = g_deg[i]; loc += d; mx = max(mx, d); }
    sums[t] = loc;
    smax[t] = mx;
    __syncthreads();
    for (int off = 1; off < 1024; off <<= 1) {
        int v = (t >= off) ? sums[t - off] : 0;
        __syncthreads();
        sums[t] += v;
        __syncthreads();
    }
    int run = (t == 0) ? 0 : sums[t - 1];
    for (int i = s; i < e; i++) {
        int d = g_deg[i];
        g_rowptr[i] = run;
        g_wptr[i]   = run;
        g_dinv[i]   = (d > 0) ? (1.0f / (float)d) : 0.0f;
        run += d;
    }
    for (int off = 512; off > 0; off >>= 1) {
        if (t < off) smax[t] = max(smax[t], smax[t + off]);
        __syncthreads();
    }
    if (t == 0) g_degmax = max(smax[0], 1);
}

// merged: CSR fill (threads [0,E)) + node init (threads [E, E+n*64))
__global__ void k_fillinit(const int* __restrict__ row, const int* __restrict__ col,
                           const float* __restrict__ x, const float* __restrict__ Wi,
                           const float* __restrict__ We1, int E, int n, int nobs) {
    int i = blockIdx.x * blockDim.x + threadIdx.x;
    if (i < E) {
        int p = atomicAdd(&g_wptr[col[i]], 1);
        g_srcidx[p] = row[i];
    } else {
        int t = i - E;
        if (t >= n * 64) return;
        int node = t >> 6, c = t & 63;
        const float* xr = x + node * nobs;
        float s1 = 0.f, s2 = 0.f;
        for (int j = 0; j < nobs; j++) {
            float xv = __ldg(&xr[j]);
            s1 += xv * __ldg(&Wi[j * 64 + c]);
            if (c < 63) s2 += xv * __ldg(&We1[j * 63 + c]);
        }
        g_curA[t] = fmaxf(s1, 0.f);
        g_h[t]    = (c < 63) ? fmaxf(s2, 0.f) : 0.f;
    }
}

// fused double gather: outH = mean of h rows (+deg col), outC = mean of cur rows
__global__ void k_dgather(const float* __restrict__ h, const float* __restrict__ cur,
                          float* __restrict__ outH, float* __restrict__ outC, int n) {
    int hw = (blockIdx.x * blockDim.x + threadIdx.x) >> 4;
    int lane = threadIdx.x & 15;
    if (hw >= n) return;
    int start = g_rowptr[hw];
    int d = g_deg[hw];
    const float4* h4 = (const float4*)h;
    const float4* c4 = (const float4*)cur;
    float hx = 0.f, hy = 0.f, hz = 0.f, hw_ = 0.f;
    float cx = 0.f, cy = 0.f, cz = 0.f, cw = 0.f;
    int i = 0;
    for (; i + 4 <= d; i += 4) {
        int s0 = __ldg(&g_srcidx[start + i]);
        int s1 = __ldg(&g_srcidx[start + i + 1]);
        int s2 = __ldg(&g_srcidx[start + i + 2]);
        int s3 = __ldg(&g_srcidx[start + i + 3]);
        float4 a0 = __ldg(&h4[s0 * 16 + lane]);
        float4 a1 = __ldg(&h4[s1 * 16 + lane]);
        float4 a2 = __ldg(&h4[s2 * 16 + lane]);
        float4 a3 = __ldg(&h4[s3 * 16 + lane]);
        float4 b0 = __ldg(&c4[s0 * 16 + lane]);
        float4 b1 = __ldg(&c4[s1 * 16 + lane]);
        float4 b2 = __ldg(&c4[s2 * 16 + lane]);
        float4 b3 = __ldg(&c4[s3 * 16 + lane]);
        hx += (a0.x + a1.x) + (a2.x + a3.x);
        hy += (a0.y + a1.y) + (a2.y + a3.y);
        hz += (a0.z + a1.z) + (a2.z + a3.z);
        hw_ += (a0.w + a1.w) + (a2.w + a3.w);
        cx += (b0.x + b1.x) + (b2.x + b3.x);
        cy += (b0.y + b1.y) + (b2.y + b3.y);
        cz += (b0.z + b1.z) + (b2.z + b3.z);
        cw += (b0.w + b1.w) + (b2.w + b3.w);
    }
    for (; i < d; i++) {
        int s = __ldg(&g_srcidx[start + i]);
        float4 a = __ldg(&h4[s * 16 + lane]);
        float4 b = __ldg(&c4[s * 16 + lane]);
        hx += a.x; hy += a.y; hz += a.z; hw_ += a.w;
        cx += b.x; cy += b.y; cz += b.z; cw += b.w;
    }
    float sc = g_dinv[hw];
    hx *= sc; hy *= sc; hz *= sc; hw_ *= sc;
    cx *= sc; cy *= sc; cz *= sc; cw *= sc;
    if (lane == 15) hw_ = (float)d / (float)g_degmax;
    ((float4*)outH)[hw * 16 + lane] = make_float4(hx, hy, hz, hw_);
    ((float4*)outC)[hw * 16 + lane] = make_float4(cx, cy, cz, cw);
}

// single gather
__global__ void k_gather(const float* __restrict__ feat, float* __restrict__ out, int n) {
    int hw = (blockIdx.x * blockDim.x + threadIdx.x) >> 4;
    int lane = threadIdx.x & 15;
    if (hw >= n) return;
    int start = g_rowptr[hw];
    int d = g_deg[hw];
    const float4* f4 = (const float4*)feat;
    float ax = 0.f, ay = 0.f, az = 0.f, aw = 0.f;
    int i = 0;
    for (; i + 4 <= d; i += 4) {
        int s0 = __ldg(&g_srcidx[start + i]);
        int s1 = __ldg(&g_srcidx[start + i + 1]);
        int s2 = __ldg(&g_srcidx[start + i + 2]);
        int s3 = __ldg(&g_srcidx[start + i + 3]);
        float4 v0 = __ldg(&f4[s0 * 16 + lane]);
        float4 v1 = __ldg(&f4[s1 * 16 + lane]);
        float4 v2 = __ldg(&f4[s2 * 16 + lane]);
        float4 v3 = __ldg(&f4[s3 * 16 + lane]);
        ax += (v0.x + v1.x) + (v2.x + v3.x);
        ay += (v0.y + v1.y) + (v2.y + v3.y);
        az += (v0.z + v1.z) + (v2.z + v3.z);
        aw += (v0.w + v1.w) + (v2.w + v3.w);
    }
    for (; i < d; i++) {
        int s = __ldg(&g_srcidx[start + i]);
        float4 v = __ldg(&f4[s * 16 + lane]);
        ax += v.x; ay += v.y; az += v.z; aw += v.w;
    }
    float sc = g_dinv[hw];
    ((float4*)out)[hw * 16 + lane] = make_float4(ax * sc, ay * sc, az * sc, aw * sc);
}

// ---------------------------------------------------------------------------
// GEMM core, 8 rows x 8 cols per thread.  128 threads: q = tid&7 (col group
// q*8), rr = tid>>3 (0..15), rows rr + 16j, j=0..7.  acc[j][0..3] = 4 f32x2.
template <int K, int PITCH>
__device__ __forceinline__ void gemm_core8x8(const float* __restrict__ ins,
                                             const float* __restrict__ Ws,
                                             ull acc[8][4]) {
    int q  = threadIdx.x & 7;
    int rr = threadIdx.x >> 3;
#pragma unroll
    for (int j = 0; j < 8; j++)
#pragma unroll
        for (int m = 0; m < 4; m++) acc[j][m] = 0ull;

#pragma unroll 1
    for (int k = 0; k < K; k += 4) {
        float4 a[8];
#pragma unroll
        for (int j = 0; j < 8; j++)
            a[j] = *(const float4*)&ins[(rr + 16 * j) * PITCH + k];
#pragma unroll
        for (int kk = 0; kk < 4; kk++) {
            ulonglong2 w = *(const ulonglong2*)&Ws[(k + kk) * 64 + q * 8];
            ulonglong2 w2 = *(const ulonglong2*)&Ws[(k + kk) * 64 + q * 8 + 4];
#pragma unroll
            for (int j = 0; j < 8; j++) {
                float av = (kk == 0) ? a[j].x : (kk == 1) ? a[j].y
                         : (kk == 2) ? a[j].z : a[j].w;
                ull p;
                asm("mov.b64 %0, {%1, %1};" : "=l"(p) : "f"(av));
                asm("fma.rn.f32x2 %0, %1, %2, %0;" : "+l"(acc[j][0]) : "l"(p), "l"(w.x));
                asm("fma.rn.f32x2 %0, %1, %2, %0;" : "+l"(acc[j][1]) : "l"(p), "l"(w.y));
                asm("fma.rn.f32x2 %0, %1, %2, %0;" : "+l"(acc[j][2]) : "l"(p), "l"(w2.x));
                asm("fma.rn.f32x2 %0, %1, %2, %0;" : "+l"(acc[j][3]) : "l"(p), "l"(w2.y));
            }
        }
    }
}

__device__ __forceinline__ float4 acc_relu4(ull a0, ull a1) {
    float lo0, hi0, lo1, hi1;
    asm("mov.b64 {%0, %1}, %2;" : "=f"(lo0), "=f"(hi0) : "l"(a0));
    asm("mov.b64 {%0, %1}, %2;" : "=f"(lo1), "=f"(hi1) : "l"(a1));
    float4 o;
    o.x = fmaxf(lo0, 0.f); o.y = fmaxf(hi0, 0.f);
    o.z = fmaxf(lo1, 0.f); o.w = fmaxf(hi1, 0.f);
    return o;
}

// C = relu( concat(A,B) @ W[128,64] ), 128 nodes / 128-thread block.
template <bool LAST>
__global__ __launch_bounds__(128) void k_gemm128(const float* __restrict__ A,
                                                 const float* __restrict__ B,
                                                 const float* __restrict__ W,
                                                 float* __restrict__ C,
                                                 const float* __restrict__ Wr,
                                                 const int* __restrict__ batch,
                                                 float* __restrict__ out, int n) {
    extern __shared__ float sm[];
    const int PITCH = 132;
    float* Ws  = sm;                 // 128*64
    float* ins = sm + 128 * 64;      // 128*PITCH
    __shared__ float Wrs[64];
    int tid = threadIdx.x;
    int node0 = blockIdx.x * 128;

    for (int idx = tid; idx < 128 * 16; idx += 128)
        ((float4*)Ws)[idx] = __ldg((const float4*)W + idx);
    if (LAST && tid < 64) Wrs[tid] = __ldg(&Wr[64 + tid]);

    for (int idx = tid; idx < 2048; idx += 128) {
        int r = idx >> 4, c4 = (idx & 15) << 2;
        int node = node0 + r;
        float4 va = make_float4(0.f, 0.f, 0.f, 0.f), vb = va;
        if (node < n) {
            va = __ldg((const float4*)&A[(size_t)node * 64 + c4]);
            vb = __ldg((const float4*)&B[(size_t)node * 64 + c4]);
        }
        *(float4*)&ins[r * PITCH + c4]      = va;
        *(float4*)&ins[r * PITCH + 64 + c4] = vb;
    }
    __syncthreads();

    ull acc[8][4];
    gemm_core8x8<128, PITCH>(ins, Ws, acc);

    int q  = tid & 7;
    int rr = tid >> 3;

    float4 o[8][2];
#pragma unroll
    for (int j = 0; j < 8; j++) {
        o[j][0] = acc_relu4(acc[j][0], acc[j][1]);
        o[j][1] = acc_relu4(acc[j][2], acc[j][3]);
    }

    if (!LAST) {
#pragma unroll
        for (int j = 0; j < 8; j++) {
            int node = node0 + rr + 16 * j;
            if (node < n) {
                float* Cr = &C[(size_t)node * 64 + q * 8];
                *(float4*)&Cr[0] = o[j][0];
                *(float4*)&Cr[4] = o[j][1];
            }
        }
    } else {
        // per-node dot with W_read[64:]; threads sharing a row are 8
        // consecutive lanes (same rr) -> xor-shuffle reduce over 1,2,4
        const float* wv = &Wrs[q * 8];
        float4 w0 = *(const float4*)&wv[0];
        float4 w1 = *(const float4*)&wv[4];
#pragma unroll
        for (int j = 0; j < 8; j++) {
            float dv = o[j][0].x * w0.x + o[j][0].y * w0.y + o[j][0].z * w0.z + o[j][0].w * w0.w
                     + o[j][1].x * w1.x + o[j][1].y * w1.y + o[j][1].z * w1.z + o[j][1].w * w1.w;
            dv += __shfl_xor_sync(0xffffffffu, dv, 1);
            dv += __shfl_xor_sync(0xffffffffu, dv, 2);
            dv += __shfl_xor_sync(0xffffffffu, dv, 4);
            int node = node0 + rr + 16 * j;
            if (q == 0 && node < n) out[node] = dv;
        }
        // stash relu'd rows for the per-graph segmented reduce
        __syncthreads();
#pragma unroll
        for (int j = 0; j < 8; j++) {
            float* dst = &ins[(rr + 16 * j) * PITCH + q * 8];
            *(float4*)&dst[0] = o[j][0];
            *(float4*)&dst[4] = o[j][1];
        }
        __syncthreads();
        if (tid < 64) {
            int c = tid;
            float acc2 = 0.f, cnt = 0.f;
            int curb = -1;
            for (int i = 0; i < 128; i++) {
                int node = node0 + i;
                if (node >= n) break;
                int b = __ldg(&batch[node]);
                if (b != curb) {
                    if (curb >= 0) {
                        atomicAdd(&g_means[curb * 64 + c], acc2);
                        if (c == 0) atomicAdd(&g_cnt[curb], cnt);
                    }
                    acc2 = 0.f; cnt = 0.f; curb = b;
                }
                acc2 += ins[i * PITCH + c];
                cnt += 1.f;
            }
            if (curb >= 0) {
                atomicAdd(&g_means[curb * 64 + c], acc2);
                if (c == 0) atomicAdd(&g_cnt[curb], cnt);
            }
        }
    }
}

// eemb = relu( naggH @ We2 ), K=64, 128 nodes / 128-thread block
__global__ __launch_bounds__(128) void k_gemm64(const float* __restrict__ A,
                                                const float* __restrict__ W,
                                                float* __restrict__ C, int n) {
    extern __shared__ float sm[];
    const int PITCH = 68;
    float* Ws  = sm;               // 64*64
    float* ins = sm + 64 * 64;     // 128*68
    int tid = threadIdx.x;
    int node0 = blockIdx.x * 128;

    for (int idx = tid; idx < 64 * 16; idx += 128)
        ((float4*)Ws)[idx] = __ldg((const float4*)W + idx);
    for (int idx = tid; idx < 2048; idx += 128) {
        int r = idx >> 4, c4 = (idx & 15) << 2;
        int node = node0 + r;
        float4 va = (node < n) ? __ldg((const float4*)&A[(size_t)node * 64 + c4])
                               : make_float4(0.f, 0.f, 0.f, 0.f);
        *(float4*)&ins[r * PITCH + c4] = va;
    }
    __syncthreads();

    ull acc[8][4];
    gemm_core8x8<64, PITCH>(ins, Ws, acc);

    int q  = tid & 7;
    int rr = tid >> 3;
#pragma unroll
    for (int j = 0; j < 8; j++) {
        int node = node0 + rr + 16 * j;
        if (node < n) {
            float* Cr = &C[(size_t)node * 64 + q * 8];
            *(float4*)&Cr[0] = acc_relu4(acc[j][0], acc[j][1]);
            *(float4*)&Cr[4] = acc_relu4(acc[j][2], acc[j][3]);
        }
    }
}

// gconst[g] = relu(mean_g @ W_pool) . W_read[:64] + b_read
__global__ void k_gconst(const float* __restrict__ Wp, const float* __restrict__ Wr,
                         const float* __restrict__ br) {
    int g = blockIdx.x;
    int t = threadIdx.x;  // 64 threads
    __shared__ float m[64];
    __shared__ float red[64];
    float cnt = g_cnt[g];
    if (cnt <= 0.f) { if (t == 0) g_gconst[g] = 0.f; return; }
    m[t] = g_means[g * 64 + t] / cnt;
    __syncthreads();
    float p = 0.f;
#pragma unroll 8
    for (int k = 0; k < 64; k++) p += m[k] * __ldg(&Wp[k * 64 + t]);
    red[t] = fmaxf(p, 0.f) * __ldg(&Wr[t]);
    __syncthreads();
    if (t < 32) {
        float s = red[t] + red[t + 32];
#pragma unroll
        for (int off = 16; off > 0; off >>= 1) s += __shfl_down_sync(0xffffffffu, s, off);
        if (t == 0) g_gconst[g] = s + __ldg(&br[0]);
    }
}

// out[i] += gconst[batch[i]]
__global__ void k_addg(const int* __restrict__ batch, float* __restrict__ out, int n) {
    int i = blockIdx.x * blockDim.x + threadIdx.x;
    if (i < n) out[i] += g_gconst[__ldg(&batch[i])];
}

// ---------------------------------------------------------------------------
extern "C" void kernel_launch(void* const* d_in, const int* in_sizes, int n_in,
                              void* d_out, int out_size) {
    const float* x    = (const float*)d_in[0];
    const float* Wi   = (const float*)d_in[1];
    const float* We1  = (const float*)d_in[2];
    const float* We2  = (const float*)d_in[3];
    const float* Wmsg = (const float*)d_in[4];
    const float* Wupd = (const float*)d_in[5];
    const float* Wp   = (const float*)d_in[6];
    const float* Wr   = (const float*)d_in[7];
    const float* br   = (const float*)d_in[8];
    const int*   eidx = (const int*)d_in[9];
    const int*   batch= (const int*)d_in[10];

    int n    = in_sizes[10];
    int E    = in_sizes[9] / 2;
    int nobs = in_sizes[0] / n;
    int L    = in_sizes[4] / (128 * 64);
    const int* row = eidx;
    const int* col = eidx + E;
    float* out = (float*)d_out;

    float *curA, *curB, *hbuf, *nagg, *naggH, *msg, *eemb, *means, *cnt;
    int* deg;
    cudaGetSymbolAddress((void**)&curA, g_curA);
    cudaGetSymbolAddress((void**)&curB, g_curB);
    cudaGetSymbolAddress((void**)&hbuf, g_h);
    cudaGetSymbolAddress((void**)&nagg, g_nagg);
    cudaGetSymbolAddress((void**)&naggH, g_naggH);
    cudaGetSymbolAddress((void**)&msg,  g_msg);
    cudaGetSymbolAddress((void**)&eemb, g_eemb);
    cudaGetSymbolAddress((void**)&means, g_means);
    cudaGetSymbolAddress((void**)&cnt,   g_cnt);
    cudaGetSymbolAddress((void**)&deg,   g_deg);

    const int SMEM128 = (128 * 64 + 128 * 132) * 4;  // 100352
    const int SMEM64  = (64 * 64 + 128 * 68) * 4;    // 51200
    cudaFuncSetAttribute(k_gemm128<false>, cudaFuncAttributeMaxDynamicSharedMemorySize, SMEM128);
    cudaFuncSetAttribute(k_gemm128<true>,  cudaFuncAttributeMaxDynamicSharedMemorySize, SMEM128);
    cudaFuncSetAttribute(k_gemm64, cudaFuncAttributeMaxDynamicSharedMemorySize, SMEM64);

    int gE  = (E + 255) / 256;
    int gFI = (E + n * 64 + 255) / 256;
    int gHW = (n * 16 + 255) / 256;
    int gG  = (n + 127) / 128;
    int gA  = (n + 255) / 256;

    cudaMemsetAsync(deg,   0, (size_t)n * sizeof(int));
    cudaMemsetAsync(means, 0, (size_t)MAXG * FD * sizeof(float));
    cudaMemsetAsync(cnt,   0, (size_t)MAXG * sizeof(float));

    k_deg<<<gE, 256>>>(col, E);
    k_scan<<<1, 1024>>>(n);
    k_fillinit<<<gFI, 256>>>(row, col, x, Wi, We1, E, n, nobs);
    k_dgather<<<gHW, 256>>>(hbuf, curA, naggH, nagg, n);   // profiled slot

    k_gemm64<<<gG, 128, SMEM64>>>(naggH, We2, eemb, n);

    float* cin = curA;
    float* cout = curB;
    for (int l = 0; l < L; l++) {
        bool last = (l == L - 1);
        if (l > 0) k_gather<<<gHW, 256>>>(cin, nagg, n);
        k_gemm128<false><<<gG, 128, SMEM128>>>(nagg, eemb, Wmsg + (size_t)l * 8192, msg,
                                               nullptr, nullptr, nullptr, n);
        if (!last) {
            k_gemm128<false><<<gG, 128, SMEM128>>>(cin, msg, Wupd + (size_t)l * 8192, cout,
                                                   nullptr, nullptr, nullptr, n);
            float* tmp = cin; cin = cout; cout = tmp;
        } else {
            k_gemm128<true><<<gG, 128, SMEM128>>>(cin, msg, Wupd + (size_t)l * 8192, nullptr,
                                                  Wr, batch, out, n);
        }
    }

    k_gconst<<<MAXG, 64>>>(Wp, Wr, br);
    k_addg<<<gA, 256>>>(batch, out, n);
}

// round 7
// speedup vs baseline: 1.0967x; 1.0561x over previous
#include <cuda_runtime.h>
#include <cuda_bf16.h>
#include <math.h>

// ---------------------------------------------------------------------------
// MPNN on GB300 (round 7).
//  - k_layer2: GEMM1(Wmsg)+GEMM2(Wupd) fused in one kernel (gather stays
//    separate). Single ins buffer: msg overwrites eemb-half, cur loads into
//    nagg-half, W reloaded between phases. 100KB smem -> 2 blocks/SM.
//  - Kills the msg global round-trip and 1 launch per layer.
//  - GEMM core: 8 rows x 8 cols per thread, fma.rn.f32x2.
// ---------------------------------------------------------------------------

#define MAXN 65536
#define MAXE 1048576
#define MAXG 512
#define FD   64

typedef unsigned long long ull;

__device__ int   g_deg[MAXN];
__device__ int   g_rowptr[MAXN];
__device__ int   g_wptr[MAXN];
__device__ int   g_srcidx[MAXE];
__device__ float g_dinv[MAXN];
__device__ int   g_degmax;

__device__ float g_h[MAXN * FD];
__device__ float g_nagg[MAXN * FD];
__device__ float g_naggH[MAXN * FD];
__device__ float g_eemb[MAXN * FD];
__device__ float g_curA[MAXN * FD];
__device__ float g_curB[MAXN * FD];

__device__ float g_means[MAXG * FD];
__device__ float g_cnt[MAXG];
__device__ float g_gconst[MAXG];

// ---------------------------------------------------------------------------
__global__ void k_deg(const int* __restrict__ col, int E) {
    int i = blockIdx.x * blockDim.x + threadIdx.x;
    if (i < E) atomicAdd(&g_deg[col[i]], 1);
}

__global__ void k_scan(int n) {
    __shared__ int sums[1024];
    __shared__ int smax[1024];
    int t = threadIdx.x;
    int chunk = (n + 1023) >> 10;
    int s = t * chunk;
    int e = min(s + chunk, n);
    int loc = 0, mx = 0;
    for (int i = s; i < e; i++) { int d = g_deg[i]; loc += d; mx = max(mx, d); }
    sums[t] = loc;
    smax[t] = mx;
    __syncthreads();
    for (int off = 1; off < 1024; off <<= 1) {
        int v = (t >= off) ? sums[t - off] : 0;
        __syncthreads();
        sums[t] += v;
        __syncthreads();
    }
    int run = (t == 0) ? 0 : sums[t - 1];
    for (int i = s; i < e; i++) {
        int d = g_deg[i];
        g_rowptr[i] = run;
        g_wptr[i]   = run;
        g_dinv[i]   = (d > 0) ? (1.0f / (float)d) : 0.0f;
        run += d;
    }
    for (int off = 512; off > 0; off >>= 1) {
        if (t < off) smax[t] = max(smax[t], smax[t + off]);
        __syncthreads();
    }
    if (t == 0) g_degmax = max(smax[0], 1);
}

// merged: CSR fill (threads [0,E)) + node init (threads [E, E+n*64))
__global__ void k_fillinit(const int* __restrict__ row, const int* __restrict__ col,
                           const float* __restrict__ x, const float* __restrict__ Wi,
                           const float* __restrict__ We1, int E, int n, int nobs) {
    int i = blockIdx.x * blockDim.x + threadIdx.x;
    if (i < E) {
        int p = atomicAdd(&g_wptr[col[i]], 1);
        g_srcidx[p] = row[i];
    } else {
        int t = i - E;
        if (t >= n * 64) return;
        int node = t >> 6, c = t & 63;
        const float* xr = x + node * nobs;
        float s1 = 0.f, s2 = 0.f;
        for (int j = 0; j < nobs; j++) {
            float xv = __ldg(&xr[j]);
            s1 += xv * __ldg(&Wi[j * 64 + c]);
            if (c < 63) s2 += xv * __ldg(&We1[j * 63 + c]);
        }
        g_curA[t] = fmaxf(s1, 0.f);
        g_h[t]    = (c < 63) ? fmaxf(s2, 0.f) : 0.f;
    }
}

// fused double gather: outH = mean of h rows (+deg col), outC = mean of cur rows
__global__ void k_dgather(const float* __restrict__ h, const float* __restrict__ cur,
                          float* __restrict__ outH, float* __restrict__ outC, int n) {
    int hw = (blockIdx.x * blockDim.x + threadIdx.x) >> 4;
    int lane = threadIdx.x & 15;
    if (hw >= n) return;
    int start = g_rowptr[hw];
    int d = g_deg[hw];
    const float4* h4 = (const float4*)h;
    const float4* c4 = (const float4*)cur;
    float hx = 0.f, hy = 0.f, hz = 0.f, hw_ = 0.f;
    float cx = 0.f, cy = 0.f, cz = 0.f, cw = 0.f;
    int i = 0;
    for (; i + 4 <= d; i += 4) {
        int s0 = __ldg(&g_srcidx[start + i]);
        int s1 = __ldg(&g_srcidx[start + i + 1]);
        int s2 = __ldg(&g_srcidx[start + i + 2]);
        int s3 = __ldg(&g_srcidx[start + i + 3]);
        float4 a0 = __ldg(&h4[s0 * 16 + lane]);
        float4 a1 = __ldg(&h4[s1 * 16 + lane]);
        float4 a2 = __ldg(&h4[s2 * 16 + lane]);
        float4 a3 = __ldg(&h4[s3 * 16 + lane]);
        float4 b0 = __ldg(&c4[s0 * 16 + lane]);
        float4 b1 = __ldg(&c4[s1 * 16 + lane]);
        float4 b2 = __ldg(&c4[s2 * 16 + lane]);
        float4 b3 = __ldg(&c4[s3 * 16 + lane]);
        hx += (a0.x + a1.x) + (a2.x + a3.x);
        hy += (a0.y + a1.y) + (a2.y + a3.y);
        hz += (a0.z + a1.z) + (a2.z + a3.z);
        hw_ += (a0.w + a1.w) + (a2.w + a3.w);
        cx += (b0.x + b1.x) + (b2.x + b3.x);
        cy += (b0.y + b1.y) + (b2.y + b3.y);
        cz += (b0.z + b1.z) + (b2.z + b3.z);
        cw += (b0.w + b1.w) + (b2.w + b3.w);
    }
    for (; i < d; i++) {
        int s = __ldg(&g_srcidx[start + i]);
        float4 a = __ldg(&h4[s * 16 + lane]);
        float4 b = __ldg(&c4[s * 16 + lane]);
        hx += a.x; hy += a.y; hz += a.z; hw_ += a.w;
        cx += b.x; cy += b.y; cz += b.z; cw += b.w;
    }
    float sc = g_dinv[hw];
    hx *= sc; hy *= sc; hz *= sc; hw_ *= sc;
    cx *= sc; cy *= sc; cz *= sc; cw *= sc;
    if (lane == 15) hw_ = (float)d / (float)g_degmax;
    ((float4*)outH)[hw * 16 + lane] = make_float4(hx, hy, hz, hw_);
    ((float4*)outC)[hw * 16 + lane] = make_float4(cx, cy, cz, cw);
}

// single gather
__global__ void k_gather(const float* __restrict__ feat, float* __restrict__ out, int n) {
    int hw = (blockIdx.x * blockDim.x + threadIdx.x) >> 4;
    int lane = threadIdx.x & 15;
    if (hw >= n) return;
    int start = g_rowptr[hw];
    int d = g_deg[hw];
    const float4* f4 = (const float4*)feat;
    float ax = 0.f, ay = 0.f, az = 0.f, aw = 0.f;
    int i = 0;
    for (; i + 4 <= d; i += 4) {
        int s0 = __ldg(&g_srcidx[start + i]);
        int s1 = __ldg(&g_srcidx[start + i + 1]);
        int s2 = __ldg(&g_srcidx[start + i + 2]);
        int s3 = __ldg(&g_srcidx[start + i + 3]);
        float4 v0 = __ldg(&f4[s0 * 16 + lane]);
        float4 v1 = __ldg(&f4[s1 * 16 + lane]);
        float4 v2 = __ldg(&f4[s2 * 16 + lane]);
        float4 v3 = __ldg(&f4[s3 * 16 + lane]);
        ax += (v0.x + v1.x) + (v2.x + v3.x);
        ay += (v0.y + v1.y) + (v2.y + v3.y);
        az += (v0.z + v1.z) + (v2.z + v3.z);
        aw += (v0.w + v1.w) + (v2.w + v3.w);
    }
    for (; i < d; i++) {
        int s = __ldg(&g_srcidx[start + i]);
        float4 v = __ldg(&f4[s * 16 + lane]);
        ax += v.x; ay += v.y; az += v.z; aw += v.w;
    }
    float sc = g_dinv[hw];
    ((float4*)out)[hw * 16 + lane] = make_float4(ax * sc, ay * sc, az * sc, aw * sc);
}

// ---------------------------------------------------------------------------
// GEMM core, 8 rows x 8 cols per thread.  128 threads: q = tid&7 (col group
// q*8), rr = tid>>3 (0..15), rows rr + 16j, j=0..7.
template <int K, int PITCH>
__device__ __forceinline__ void gemm_core8x8(const float* __restrict__ ins,
                                             const float* __restrict__ Ws,
                                             ull acc[8][4]) {
    int q  = threadIdx.x & 7;
    int rr = threadIdx.x >> 3;
#pragma unroll
    for (int j = 0; j < 8; j++)
#pragma unroll
        for (int m = 0; m < 4; m++) acc[j][m] = 0ull;

#pragma unroll 1
    for (int k = 0; k < K; k += 4) {
        float4 a[8];
#pragma unroll
        for (int j = 0; j < 8; j++)
            a[j] = *(const float4*)&ins[(rr + 16 * j) * PITCH + k];
#pragma unroll
        for (int kk = 0; kk < 4; kk++) {
            ulonglong2 w = *(const ulonglong2*)&Ws[(k + kk) * 64 + q * 8];
            ulonglong2 w2 = *(const ulonglong2*)&Ws[(k + kk) * 64 + q * 8 + 4];
#pragma unroll
            for (int j = 0; j < 8; j++) {
                float av = (kk == 0) ? a[j].x : (kk == 1) ? a[j].y
                         : (kk == 2) ? a[j].z : a[j].w;
                ull p;
                asm("mov.b64 %0, {%1, %1};" : "=l"(p) : "f"(av));
                asm("fma.rn.f32x2 %0, %1, %2, %0;" : "+l"(acc[j][0]) : "l"(p), "l"(w.x));
                asm("fma.rn.f32x2 %0, %1, %2, %0;" : "+l"(acc[j][1]) : "l"(p), "l"(w.y));
                asm("fma.rn.f32x2 %0, %1, %2, %0;" : "+l"(acc[j][2]) : "l"(p), "l"(w2.x));
                asm("fma.rn.f32x2 %0, %1, %2, %0;" : "+l"(acc[j][3]) : "l"(p), "l"(w2.y));
            }
        }
    }
}

__device__ __forceinline__ float4 acc_relu4(ull a0, ull a1) {
    float lo0, hi0, lo1, hi1;
    asm("mov.b64 {%0, %1}, %2;" : "=f"(lo0), "=f"(hi0) : "l"(a0));
    asm("mov.b64 {%0, %1}, %2;" : "=f"(lo1), "=f"(hi1) : "l"(a1));
    float4 o;
    o.x = fmaxf(lo0, 0.f); o.y = fmaxf(hi0, 0.f);
    o.z = fmaxf(lo1, 0.f); o.w = fmaxf(hi1, 0.f);
    return o;
}

// Fused layer: msg = relu(concat(nagg, eemb) @ Wmsg);
//              cout = relu(concat(cur, msg) @ Wupd).
// One ins buffer: phase B writes msg over the eemb half, loads cur over the
// nagg half, reloads W. LAST variant fuses the readout instead of writing cout.
template <bool LAST>
__global__ __launch_bounds__(128) void k_layer2(const float* __restrict__ nagg,
                                                const float* __restrict__ eemb,
                                                const float* __restrict__ cur,
                                                const float* __restrict__ Wmsg,
                                                const float* __restrict__ Wupd,
                                                float* __restrict__ cout,
                                                const float* __restrict__ Wr,
                                                const int* __restrict__ batch,
                                                float* __restrict__ out, int n) {
    extern __shared__ float sm[];
    const int PITCH = 132;
    float* Ws  = sm;                 // 128*64
    float* ins = sm + 128 * 64;      // 128*PITCH
    __shared__ float Wrs[64];
    int tid = threadIdx.x;
    int node0 = blockIdx.x * 128;
    int q  = tid & 7;
    int rr = tid >> 3;

    // phase A: Wmsg, [nagg | eemb]
    for (int idx = tid; idx < 128 * 16; idx += 128)
        ((float4*)Ws)[idx] = __ldg((const float4*)Wmsg + idx);
    if (LAST && tid < 64) Wrs[tid] = __ldg(&Wr[64 + tid]);
    for (int idx = tid; idx < 2048; idx += 128) {
        int r = idx >> 4, c4 = (idx & 15) << 2;
        int node = node0 + r;
        float4 va = make_float4(0.f, 0.f, 0.f, 0.f), vb = va;
        if (node < n) {
            va = __ldg((const float4*)&nagg[(size_t)node * 64 + c4]);
            vb = __ldg((const float4*)&eemb[(size_t)node * 64 + c4]);
        }
        *(float4*)&ins[r * PITCH + c4]      = va;
        *(float4*)&ins[r * PITCH + 64 + c4] = vb;
    }
    __syncthreads();

    // phase B: GEMM1
    ull acc[8][4];
    gemm_core8x8<128, PITCH>(ins, Ws, acc);
    float4 o[8][2];
#pragma unroll
    for (int j = 0; j < 8; j++) {
        o[j][0] = acc_relu4(acc[j][0], acc[j][1]);
        o[j][1] = acc_relu4(acc[j][2], acc[j][3]);
    }
    __syncthreads();   // all reads of ins done

    // msg -> eemb half; cur -> nagg half; Wupd -> Ws
#pragma unroll
    for (int j = 0; j < 8; j++) {
        float* dst = &ins[(rr + 16 * j) * PITCH + 64 + q * 8];
        *(float4*)&dst[0] = o[j][0];
        *(float4*)&dst[4] = o[j][1];
    }
    for (int idx = tid; idx < 2048; idx += 128) {
        int r = idx >> 4, c4 = (idx & 15) << 2;
        int node = node0 + r;
        float4 vc = (node < n) ? __ldg((const float4*)&cur[(size_t)node * 64 + c4])
                               : make_float4(0.f, 0.f, 0.f, 0.f);
        *(float4*)&ins[r * PITCH + c4] = vc;
    }
    for (int idx = tid; idx < 128 * 16; idx += 128)
        ((float4*)Ws)[idx] = __ldg((const float4*)Wupd + idx);
    __syncthreads();

    // phase C: GEMM2
    gemm_core8x8<128, PITCH>(ins, Ws, acc);
#pragma unroll
    for (int j = 0; j < 8; j++) {
        o[j][0] = acc_relu4(acc[j][0], acc[j][1]);
        o[j][1] = acc_relu4(acc[j][2], acc[j][3]);
    }

    if (!LAST) {
#pragma unroll
        for (int j = 0; j < 8; j++) {
            int node = node0 + rr + 16 * j;
            if (node < n) {
                float* Cr = &cout[(size_t)node * 64 + q * 8];
                *(float4*)&Cr[0] = o[j][0];
                *(float4*)&Cr[4] = o[j][1];
            }
        }
    } else {
        const float* wv = &Wrs[q * 8];
        float4 w0 = *(const float4*)&wv[0];
        float4 w1 = *(const float4*)&wv[4];
#pragma unroll
        for (int j = 0; j < 8; j++) {
            float dv = o[j][0].x * w0.x + o[j][0].y * w0.y + o[j][0].z * w0.z + o[j][0].w * w0.w
                     + o[j][1].x * w1.x + o[j][1].y * w1.y + o[j][1].z * w1.z + o[j][1].w * w1.w;
            dv += __shfl_xor_sync(0xffffffffu, dv, 1);
            dv += __shfl_xor_sync(0xffffffffu, dv, 2);
            dv += __shfl_xor_sync(0xffffffffu, dv, 4);
            int node = node0 + rr + 16 * j;
            if (q == 0 && node < n) out[node] = dv;
        }
        __syncthreads();
#pragma unroll
        for (int j = 0; j < 8; j++) {
            float* dst = &ins[(rr + 16 * j) * PITCH + q * 8];
            *(float4*)&dst[0] = o[j][0];
            *(float4*)&dst[4] = o[j][1];
        }
        __syncthreads();
        if (tid < 64) {
            int c = tid;
            float acc2 = 0.f, cnt = 0.f;
            int curb = -1;
            for (int i = 0; i < 128; i++) {
                int node = node0 + i;
                if (node >= n) break;
                int b = __ldg(&batch[node]);
                if (b != curb) {
                    if (curb >= 0) {
                        atomicAdd(&g_means[curb * 64 + c], acc2);
                        if (c == 0) atomicAdd(&g_cnt[curb], cnt);
                    }
                    acc2 = 0.f; cnt = 0.f; curb = b;
                }
                acc2 += ins[i * PITCH + c];
                cnt += 1.f;
            }
            if (curb >= 0) {
                atomicAdd(&g_means[curb * 64 + c], acc2);
                if (c == 0) atomicAdd(&g_cnt[curb], cnt);
            }
        }
    }
}

// eemb = relu( naggH @ We2 ), K=64, 128 nodes / 128-thread block
__global__ __launch_bounds__(128) void k_gemm64(const float* __restrict__ A,
                                                const float* __restrict__ W,
                                                float* __restrict__ C, int n) {
    extern __shared__ float sm[];
    const int PITCH = 68;
    float* Ws  = sm;               // 64*64
    float* ins = sm + 64 * 64;     // 128*68
    int tid = threadIdx.x;
    int node0 = blockIdx.x * 128;

    for (int idx = tid; idx < 64 * 16; idx += 128)
        ((float4*)Ws)[idx] = __ldg((const float4*)W + idx);
    for (int idx = tid; idx < 2048; idx += 128) {
        int r = idx >> 4, c4 = (idx & 15) << 2;
        int node = node0 + r;
        float4 va = (node < n) ? __ldg((const float4*)&A[(size_t)node * 64 + c4])
                               : make_float4(0.f, 0.f, 0.f, 0.f);
        *(float4*)&ins[r * PITCH + c4] = va;
    }
    __syncthreads();

    ull acc[8][4];
    gemm_core8x8<64, PITCH>(ins, Ws, acc);

    int q  = tid & 7;
    int rr = tid >> 3;
#pragma unroll
    for (int j = 0; j < 8; j++) {
        int node = node0 + rr + 16 * j;
        if (node < n) {
            float* Cr = &C[(size_t)node * 64 + q * 8];
            *(float4*)&Cr[0] = acc_relu4(acc[j][0], acc[j][1]);
            *(float4*)&Cr[4] = acc_relu4(acc[j][2], acc[j][3]);
        }
    }
}

// gconst[g] = relu(mean_g @ W_pool) . W_read[:64] + b_read
__global__ void k_gconst(const float* __restrict__ Wp, const float* __restrict__ Wr,
                         const float* __restrict__ br) {
    int g = blockIdx.x;
    int t = threadIdx.x;  // 64 threads
    __shared__ float m[64];
    __shared__ float red[64];
    float cnt = g_cnt[g];
    if (cnt <= 0.f) { if (t == 0) g_gconst[g] = 0.f; return; }
    m[t] = g_means[g * 64 + t] / cnt;
    __syncthreads();
    float p = 0.f;
#pragma unroll 8
    for (int k = 0; k < 64; k++) p += m[k] * __ldg(&Wp[k * 64 + t]);
    red[t] = fmaxf(p, 0.f) * __ldg(&Wr[t]);
    __syncthreads();
    if (t < 32) {
        float s = red[t] + red[t + 32];
#pragma unroll
        for (int off = 16; off > 0; off >>= 1) s += __shfl_down_sync(0xffffffffu, s, off);
        if (t == 0) g_gconst[g] = s + __ldg(&br[0]);
    }
}

// out[i] += gconst[batch[i]]
__global__ void k_addg(const int* __restrict__ batch, float* __restrict__ out, int n) {
    int i = blockIdx.x * blockDim.x + threadIdx.x;
    if (i < n) out[i] += g_gconst[__ldg(&batch[i])];
}

// ---------------------------------------------------------------------------
extern "C" void kernel_launch(void* const* d_in, const int* in_sizes, int n_in,
                              void* d_out, int out_size) {
    const float* x    = (const float*)d_in[0];
    const float* Wi   = (const float*)d_in[1];
    const float* We1  = (const float*)d_in[2];
    const float* We2  = (const float*)d_in[3];
    const float* Wmsg = (const float*)d_in[4];
    const float* Wupd = (const float*)d_in[5];
    const float* Wp   = (const float*)d_in[6];
    const float* Wr   = (const float*)d_in[7];
    const float* br   = (const float*)d_in[8];
    const int*   eidx = (const int*)d_in[9];
    const int*   batch= (const int*)d_in[10];

    int n    = in_sizes[10];
    int E    = in_sizes[9] / 2;
    int nobs = in_sizes[0] / n;
    int L    = in_sizes[4] / (128 * 64);
    const int* row = eidx;
    const int* col = eidx + E;
    float* out = (float*)d_out;

    float *curA, *curB, *hbuf, *nagg, *naggH, *eemb, *means, *cnt;
    int* deg;
    cudaGetSymbolAddress((void**)&curA, g_curA);
    cudaGetSymbolAddress((void**)&curB, g_curB);
    cudaGetSymbolAddress((void**)&hbuf, g_h);
    cudaGetSymbolAddress((void**)&nagg, g_nagg);
    cudaGetSymbolAddress((void**)&naggH, g_naggH);
    cudaGetSymbolAddress((void**)&eemb, g_eemb);
    cudaGetSymbolAddress((void**)&means, g_means);
    cudaGetSymbolAddress((void**)&cnt,   g_cnt);
    cudaGetSymbolAddress((void**)&deg,   g_deg);

    const int SMEM128 = (128 * 64 + 128 * 132) * 4;  // 100352
    const int SMEM64  = (64 * 64 + 128 * 68) * 4;    // 51200
    cudaFuncSetAttribute(k_layer2<false>, cudaFuncAttributeMaxDynamicSharedMemorySize, SMEM128);
    cudaFuncSetAttribute(k_layer2<true>,  cudaFuncAttributeMaxDynamicSharedMemorySize, SMEM128);
    cudaFuncSetAttribute(k_gemm64, cudaFuncAttributeMaxDynamicSharedMemorySize, SMEM64);

    int gE  = (E + 255) / 256;
    int gFI = (E + n * 64 + 255) / 256;
    int gHW = (n * 16 + 255) / 256;
    int gG  = (n + 127) / 128;
    int gA  = (n + 255) / 256;

    cudaMemsetAsync(deg,   0, (size_t)n * sizeof(int));
    cudaMemsetAsync(means, 0, (size_t)MAXG * FD * sizeof(float));
    cudaMemsetAsync(cnt,   0, (size_t)MAXG * sizeof(float));

    k_deg<<<gE, 256>>>(col, E);
    k_scan<<<1, 1024>>>(n);
    k_fillinit<<<gFI, 256>>>(row, col, x, Wi, We1, E, n, nobs);
    k_dgather<<<gHW, 256>>>(hbuf, curA, naggH, nagg, n);   // profiled slot

    k_gemm64<<<gG, 128, SMEM64>>>(naggH, We2, eemb, n);

    float* cin = curA;
    float* cout = curB;
    for (int l = 0; l < L; l++) {
        bool last = (l == L - 1);
        if (l > 0) k_gather<<<gHW, 256>>>(cin, nagg, n);
        if (!last) {
            k_layer2<false><<<gG, 128, SMEM128>>>(nagg, eemb, cin,
                                                  Wmsg + (size_t)l * 8192,
                                                  Wupd + (size_t)l * 8192,
                                                  cout, nullptr, nullptr, nullptr, n);
            float* tmp = cin; cin = cout; cout = tmp;
        } else {
            k_layer2<true><<<gG, 128, SMEM128>>>(nagg, eemb, cin,
                                                 Wmsg + (size_t)l * 8192,
                                                 Wupd + (size_t)l * 8192,
                                                 nullptr, Wr, batch, out, n);
        }
    }

    k_gconst<<<MAXG, 64>>>(Wp, Wr, br);
    k_addg<<<gA, 256>>>(batch, out, n);
}

// round 8
// speedup vs baseline: 1.4062x; 1.2822x over previous
#include <cuda_runtime.h>
#include <cuda_bf16.h>
#include <math.h>

// ---------------------------------------------------------------------------
// MPNN on GB300 (round 8).
//  - Padded-slot adjacency (96 slots/node) built in ONE atomic pass: kills
//    k_deg + k_scan. dinv computed inline; degmax via block-max in dgather,
//    consumed in k_gemm64 staging (patches col 63 = deg/degmax).
//  - Launch order: fillpad+init -> dgather -> gemm64 -> layer2 (profiled slot).
//  - k_layer2: fused GEMM1+GEMM2 per layer, 8x8/thread, fma.rn.f32x2.
// ---------------------------------------------------------------------------

#define MAXN 65536
#define MAXG 512
#define FD   64
#define SLOT 96

typedef unsigned long long ull;

__device__ int   g_deg[MAXN];
__device__ int   g_srcpad[MAXN * SLOT];
__device__ int   g_degmax;

__device__ float g_h[MAXN * FD];
__device__ float g_nagg[MAXN * FD];
__device__ float g_naggH[MAXN * FD];
__device__ float g_eemb[MAXN * FD];
__device__ float g_curA[MAXN * FD];
__device__ float g_curB[MAXN * FD];

__device__ float g_means[MAXG * FD];
__device__ float g_cnt[MAXG];
__device__ float g_gconst[MAXG];

// ---------------------------------------------------------------------------
// One pass: edges -> padded slots (threads [0,E)) + node init (threads >= E)
__global__ void k_fillpad(const int* __restrict__ row, const int* __restrict__ col,
                          const float* __restrict__ x, const float* __restrict__ Wi,
                          const float* __restrict__ We1, int E, int n, int nobs) {
    int i = blockIdx.x * blockDim.x + threadIdx.x;
    if (i < E) {
        int c = col[i];
        int p = atomicAdd(&g_deg[c], 1);
        if (p < SLOT) g_srcpad[c * SLOT + p] = row[i];
    } else {
        int t = i - E;
        if (t >= n * 64) return;
        int node = t >> 6, c = t & 63;
        const float* xr = x + node * nobs;
        float s1 = 0.f, s2 = 0.f;
        for (int j = 0; j < nobs; j++) {
            float xv = __ldg(&xr[j]);
            s1 += xv * __ldg(&Wi[j * 64 + c]);
            if (c < 63) s2 += xv * __ldg(&We1[j * 63 + c]);
        }
        g_curA[t] = fmaxf(s1, 0.f);
        g_h[t]    = (c < 63) ? fmaxf(s2, 0.f) : 0.f;
    }
}

// fused double gather over padded slots + block degmax -> g_degmax.
// half-warp per node, float4 per lane. No early returns (block-wide syncs).
__global__ void k_dgather(const float* __restrict__ h, const float* __restrict__ cur,
                          float* __restrict__ outH, float* __restrict__ outC, int n) {
    __shared__ int ssmax;
    int tid = threadIdx.x;
    if (tid == 0) ssmax = 0;
    __syncthreads();

    int hw = (blockIdx.x * blockDim.x + tid) >> 4;
    int lane = tid & 15;
    bool valid = (hw < n);
    int d = valid ? g_deg[hw] : 0;
    int dc = min(d, SLOT);
    int base = hw * SLOT;
    const float4* h4 = (const float4*)h;
    const float4* c4 = (const float4*)cur;
    float hx = 0.f, hy = 0.f, hz = 0.f, hw_ = 0.f;
    float cx = 0.f, cy = 0.f, cz = 0.f, cw = 0.f;
    int i = 0;
    for (; i + 4 <= dc; i += 4) {
        int s0 = __ldg(&g_srcpad[base + i]);
        int s1 = __ldg(&g_srcpad[base + i + 1]);
        int s2 = __ldg(&g_srcpad[base + i + 2]);
        int s3 = __ldg(&g_srcpad[base + i + 3]);
        float4 a0 = __ldg(&h4[s0 * 16 + lane]);
        float4 a1 = __ldg(&h4[s1 * 16 + lane]);
        float4 a2 = __ldg(&h4[s2 * 16 + lane]);
        float4 a3 = __ldg(&h4[s3 * 16 + lane]);
        float4 b0 = __ldg(&c4[s0 * 16 + lane]);
        float4 b1 = __ldg(&c4[s1 * 16 + lane]);
        float4 b2 = __ldg(&c4[s2 * 16 + lane]);
        float4 b3 = __ldg(&c4[s3 * 16 + lane]);
        hx += (a0.x + a1.x) + (a2.x + a3.x);
        hy += (a0.y + a1.y) + (a2.y + a3.y);
        hz += (a0.z + a1.z) + (a2.z + a3.z);
        hw_ += (a0.w + a1.w) + (a2.w + a3.w);
        cx += (b0.x + b1.x) + (b2.x + b3.x);
        cy += (b0.y + b1.y) + (b2.y + b3.y);
        cz += (b0.z + b1.z) + (b2.z + b3.z);
        cw += (b0.w + b1.w) + (b2.w + b3.w);
    }
    for (; i < dc; i++) {
        int s = __ldg(&g_srcpad[base + i]);
        float4 a = __ldg(&h4[s * 16 + lane]);
        float4 b = __ldg(&c4[s * 16 + lane]);
        hx += a.x; hy += a.y; hz += a.z; hw_ += a.w;
        cx += b.x; cy += b.y; cz += b.z; cw += b.w;
    }
    if (valid) {
        float sc = (d > 0) ? (1.0f / (float)d) : 0.0f;
        hx *= sc; hy *= sc; hz *= sc; hw_ *= sc;
        cx *= sc; cy *= sc; cz *= sc; cw *= sc;
        if (lane == 15) hw_ = 0.f;   // patched to deg/degmax in k_gemm64 staging
        ((float4*)outH)[hw * 16 + lane] = make_float4(hx, hy, hz, hw_);
        ((float4*)outC)[hw * 16 + lane] = make_float4(cx, cy, cz, cw);
    }
    // block degmax
    if (lane == 0 && valid) atomicMax(&ssmax, d);
    __syncthreads();
    if (tid == 0) atomicMax(&g_degmax, ssmax);
}

// single gather over padded slots
__global__ void k_gather(const float* __restrict__ feat, float* __restrict__ out, int n) {
    int hw = (blockIdx.x * blockDim.x + threadIdx.x) >> 4;
    int lane = threadIdx.x & 15;
    if (hw >= n) return;
    int d = g_deg[hw];
    int dc = min(d, SLOT);
    int base = hw * SLOT;
    const float4* f4 = (const float4*)feat;
    float ax = 0.f, ay = 0.f, az = 0.f, aw = 0.f;
    int i = 0;
    for (; i + 4 <= dc; i += 4) {
        int s0 = __ldg(&g_srcpad[base + i]);
        int s1 = __ldg(&g_srcpad[base + i + 1]);
        int s2 = __ldg(&g_srcpad[base + i + 2]);
        int s3 = __ldg(&g_srcpad[base + i + 3]);
        float4 v0 = __ldg(&f4[s0 * 16 + lane]);
        float4 v1 = __ldg(&f4[s1 * 16 + lane]);
        float4 v2 = __ldg(&f4[s2 * 16 + lane]);
        float4 v3 = __ldg(&f4[s3 * 16 + lane]);
        ax += (v0.x + v1.x) + (v2.x + v3.x);
        ay += (v0.y + v1.y) + (v2.y + v3.y);
        az += (v0.z + v1.z) + (v2.z + v3.z);
        aw += (v0.w + v1.w) + (v2.w + v3.w);
    }
    for (; i < dc; i++) {
        int s = __ldg(&g_srcpad[base + i]);
        float4 v = __ldg(&f4[s * 16 + lane]);
        ax += v.x; ay += v.y; az += v.z; aw += v.w;
    }
    float sc = (d > 0) ? (1.0f / (float)d) : 0.0f;
    ((float4*)out)[hw * 16 + lane] = make_float4(ax * sc, ay * sc, az * sc, aw * sc);
}

// ---------------------------------------------------------------------------
// GEMM core, 8 rows x 8 cols per thread (128 threads, 128 nodes).
template <int K, int PITCH>
__device__ __forceinline__ void gemm_core8x8(const float* __restrict__ ins,
                                             const float* __restrict__ Ws,
                                             ull acc[8][4]) {
    int q  = threadIdx.x & 7;
    int rr = threadIdx.x >> 3;
#pragma unroll
    for (int j = 0; j < 8; j++)
#pragma unroll
        for (int m = 0; m < 4; m++) acc[j][m] = 0ull;

#pragma unroll 1
    for (int k = 0; k < K; k += 4) {
        float4 a[8];
#pragma unroll
        for (int j = 0; j < 8; j++)
            a[j] = *(const float4*)&ins[(rr + 16 * j) * PITCH + k];
#pragma unroll
        for (int kk = 0; kk < 4; kk++) {
            ulonglong2 w = *(const ulonglong2*)&Ws[(k + kk) * 64 + q * 8];
            ulonglong2 w2 = *(const ulonglong2*)&Ws[(k + kk) * 64 + q * 8 + 4];
#pragma unroll
            for (int j = 0; j < 8; j++) {
                float av = (kk == 0) ? a[j].x : (kk == 1) ? a[j].y
                         : (kk == 2) ? a[j].z : a[j].w;
                ull p;
                asm("mov.b64 %0, {%1, %1};" : "=l"(p) : "f"(av));
                asm("fma.rn.f32x2 %0, %1, %2, %0;" : "+l"(acc[j][0]) : "l"(p), "l"(w.x));
                asm("fma.rn.f32x2 %0, %1, %2, %0;" : "+l"(acc[j][1]) : "l"(p), "l"(w.y));
                asm("fma.rn.f32x2 %0, %1, %2, %0;" : "+l"(acc[j][2]) : "l"(p), "l"(w2.x));
                asm("fma.rn.f32x2 %0, %1, %2, %0;" : "+l"(acc[j][3]) : "l"(p), "l"(w2.y));
            }
        }
    }
}

__device__ __forceinline__ float4 acc_relu4(ull a0, ull a1) {
    float lo0, hi0, lo1, hi1;
    asm("mov.b64 {%0, %1}, %2;" : "=f"(lo0), "=f"(hi0) : "l"(a0));
    asm("mov.b64 {%0, %1}, %2;" : "=f"(lo1), "=f"(hi1) : "l"(a1));
    float4 o;
    o.x = fmaxf(lo0, 0.f); o.y = fmaxf(hi0, 0.f);
    o.z = fmaxf(lo1, 0.f); o.w = fmaxf(hi1, 0.f);
    return o;
}

// Fused layer: msg = relu(concat(nagg, eemb) @ Wmsg);
//              cout = relu(concat(cur, msg) @ Wupd).  LAST fuses the readout.
template <bool LAST>
__global__ __launch_bounds__(128) void k_layer2(const float* __restrict__ nagg,
                                                const float* __restrict__ eemb,
                                                const float* __restrict__ cur,
                                                const float* __restrict__ Wmsg,
                                                const float* __restrict__ Wupd,
                                                float* __restrict__ cout,
                                                const float* __restrict__ Wr,
                                                const int* __restrict__ batch,
                                                float* __restrict__ out, int n) {
    extern __shared__ float sm[];
    const int PITCH = 132;
    float* Ws  = sm;                 // 128*64
    float* ins = sm + 128 * 64;      // 128*PITCH
    __shared__ float Wrs[64];
    int tid = threadIdx.x;
    int node0 = blockIdx.x * 128;
    int q  = tid & 7;
    int rr = tid >> 3;

    for (int idx = tid; idx < 128 * 16; idx += 128)
        ((float4*)Ws)[idx] = __ldg((const float4*)Wmsg + idx);
    if (LAST && tid < 64) Wrs[tid] = __ldg(&Wr[64 + tid]);
    for (int idx = tid; idx < 2048; idx += 128) {
        int r = idx >> 4, c4 = (idx & 15) << 2;
        int node = node0 + r;
        float4 va = make_float4(0.f, 0.f, 0.f, 0.f), vb = va;
        if (node < n) {
            va = __ldg((const float4*)&nagg[(size_t)node * 64 + c4]);
            vb = __ldg((const float4*)&eemb[(size_t)node * 64 + c4]);
        }
        *(float4*)&ins[r * PITCH + c4]      = va;
        *(float4*)&ins[r * PITCH + 64 + c4] = vb;
    }
    __syncthreads();

    ull acc[8][4];
    gemm_core8x8<128, PITCH>(ins, Ws, acc);
    float4 o[8][2];
#pragma unroll
    for (int j = 0; j < 8; j++) {
        o[j][0] = acc_relu4(acc[j][0], acc[j][1]);
        o[j][1] = acc_relu4(acc[j][2], acc[j][3]);
    }
    __syncthreads();

#pragma unroll
    for (int j = 0; j < 8; j++) {
        float* dst = &ins[(rr + 16 * j) * PITCH + 64 + q * 8];
        *(float4*)&dst[0] = o[j][0];
        *(float4*)&dst[4] = o[j][1];
    }
    for (int idx = tid; idx < 2048; idx += 128) {
        int r = idx >> 4, c4 = (idx & 15) << 2;
        int node = node0 + r;
        float4 vc = (node < n) ? __ldg((const float4*)&cur[(size_t)node * 64 + c4])
                               : make_float4(0.f, 0.f, 0.f, 0.f);
        *(float4*)&ins[r * PITCH + c4] = vc;
    }
    for (int idx = tid; idx < 128 * 16; idx += 128)
        ((float4*)Ws)[idx] = __ldg((const float4*)Wupd + idx);
    __syncthreads();

    gemm_core8x8<128, PITCH>(ins, Ws, acc);
#pragma unroll
    for (int j = 0; j < 8; j++) {
        o[j][0] = acc_relu4(acc[j][0], acc[j][1]);
        o[j][1] = acc_relu4(acc[j][2], acc[j][3]);
    }

    if (!LAST) {
#pragma unroll
        for (int j = 0; j < 8; j++) {
            int node = node0 + rr + 16 * j;
            if (node < n) {
                float* Cr = &cout[(size_t)node * 64 + q * 8];
                *(float4*)&Cr[0] = o[j][0];
                *(float4*)&Cr[4] = o[j][1];
            }
        }
    } else {
        const float* wv = &Wrs[q * 8];
        float4 w0 = *(const float4*)&wv[0];
        float4 w1 = *(const float4*)&wv[4];
#pragma unroll
        for (int j = 0; j < 8; j++) {
            float dv = o[j][0].x * w0.x + o[j][0].y * w0.y + o[j][0].z * w0.z + o[j][0].w * w0.w
                     + o[j][1].x * w1.x + o[j][1].y * w1.y + o[j][1].z * w1.z + o[j][1].w * w1.w;
            dv += __shfl_xor_sync(0xffffffffu, dv, 1);
            dv += __shfl_xor_sync(0xffffffffu, dv, 2);
            dv += __shfl_xor_sync(0xffffffffu, dv, 4);
            int node = node0 + rr + 16 * j;
            if (q == 0 && node < n) out[node] = dv;
        }
        __syncthreads();
#pragma unroll
        for (int j = 0; j < 8; j++) {
            float* dst = &ins[(rr + 16 * j) * PITCH + q * 8];
            *(float4*)&dst[0] = o[j][0];
            *(float4*)&dst[4] = o[j][1];
        }
        __syncthreads();
        if (tid < 64) {
            int c = tid;
            float acc2 = 0.f, cnt = 0.f;
            int curb = -1;
            for (int i = 0; i < 128; i++) {
                int node = node0 + i;
                if (node >= n) break;
                int b = __ldg(&batch[node]);
                if (b != curb) {
                    if (curb >= 0) {
                        atomicAdd(&g_means[curb * 64 + c], acc2);
                        if (c == 0) atomicAdd(&g_cnt[curb], cnt);
                    }
                    acc2 = 0.f; cnt = 0.f; curb = b;
                }
                acc2 += ins[i * PITCH + c];
                cnt += 1.f;
            }
            if (curb >= 0) {
                atomicAdd(&g_means[curb * 64 + c], acc2);
                if (c == 0) atomicAdd(&g_cnt[curb], cnt);
            }
        }
    }
}

// eemb = relu( naggH @ We2 ), K=64; staging patches col 63 = deg/degmax
__global__ __launch_bounds__(128) void k_gemm64(const float* __restrict__ A,
                                                const float* __restrict__ W,
                                                float* __restrict__ C, int n) {
    extern __shared__ float sm[];
    const int PITCH = 68;
    float* Ws  = sm;               // 64*64
    float* ins = sm + 64 * 64;     // 128*68
    int tid = threadIdx.x;
    int node0 = blockIdx.x * 128;
    float dmx = (float)max(g_degmax, 1);

    for (int idx = tid; idx < 64 * 16; idx += 128)
        ((float4*)Ws)[idx] = __ldg((const float4*)W + idx);
    for (int idx = tid; idx < 2048; idx += 128) {
        int r = idx >> 4, c4 = (idx & 15) << 2;
        int node = node0 + r;
        float4 va = make_float4(0.f, 0.f, 0.f, 0.f);
        if (node < n) {
            va = __ldg((const float4*)&A[(size_t)node * 64 + c4]);
            if (c4 == 60) va.w = (float)g_deg[node] / dmx;
        }
        *(float4*)&ins[r * PITCH + c4] = va;
    }
    __syncthreads();

    ull acc[8][4];
    gemm_core8x8<64, PITCH>(ins, Ws, acc);

    int q  = tid & 7;
    int rr = tid >> 3;
#pragma unroll
    for (int j = 0; j < 8; j++) {
        int node = node0 + rr + 16 * j;
        if (node < n) {
            float* Cr = &C[(size_t)node * 64 + q * 8];
            *(float4*)&Cr[0] = acc_relu4(acc[j][0], acc[j][1]);
            *(float4*)&Cr[4] = acc_relu4(acc[j][2], acc[j][3]);
        }
    }
}

// gconst[g] = relu(mean_g @ W_pool) . W_read[:64] + b_read
__global__ void k_gconst(const float* __restrict__ Wp, const float* __restrict__ Wr,
                         const float* __restrict__ br) {
    int g = blockIdx.x;
    int t = threadIdx.x;
    __shared__ float m[64];
    __shared__ float red[64];
    float cnt = g_cnt[g];
    if (cnt <= 0.f) { if (t == 0) g_gconst[g] = 0.f; return; }
    m[t] = g_means[g * 64 + t] / cnt;
    __syncthreads();
    float p = 0.f;
#pragma unroll 8
    for (int k = 0; k < 64; k++) p += m[k] * __ldg(&Wp[k * 64 + t]);
    red[t] = fmaxf(p, 0.f) * __ldg(&Wr[t]);
    __syncthreads();
    if (t < 32) {
        float s = red[t] + red[t + 32];
#pragma unroll
        for (int off = 16; off > 0; off >>= 1) s += __shfl_down_sync(0xffffffffu, s, off);
        if (t == 0) g_gconst[g] = s + __ldg(&br[0]);
    }
}

// out[i] += gconst[batch[i]]
__global__ void k_addg(const int* __restrict__ batch, float* __restrict__ out, int n) {
    int i = blockIdx.x * blockDim.x + threadIdx.x;
    if (i < n) out[i] += g_gconst[__ldg(&batch[i])];
}

// ---------------------------------------------------------------------------
extern "C" void kernel_launch(void* const* d_in, const int* in_sizes, int n_in,
                              void* d_out, int out_size) {
    const float* x    = (const float*)d_in[0];
    const float* Wi   = (const float*)d_in[1];
    const float* We1  = (const float*)d_in[2];
    const float* We2  = (const float*)d_in[3];
    const float* Wmsg = (const float*)d_in[4];
    const float* Wupd = (const float*)d_in[5];
    const float* Wp   = (const float*)d_in[6];
    const float* Wr   = (const float*)d_in[7];
    const float* br   = (const float*)d_in[8];
    const int*   eidx = (const int*)d_in[9];
    const int*   batch= (const int*)d_in[10];

    int n    = in_sizes[10];
    int E    = in_sizes[9] / 2;
    int nobs = in_sizes[0] / n;
    int L    = in_sizes[4] / (128 * 64);
    const int* row = eidx;
    const int* col = eidx + E;
    float* out = (float*)d_out;

    float *curA, *curB, *hbuf, *nagg, *naggH, *eemb, *means, *cnt;
    int *deg, *degmax;
    cudaGetSymbolAddress((void**)&curA, g_curA);
    cudaGetSymbolAddress((void**)&curB, g_curB);
    cudaGetSymbolAddress((void**)&hbuf, g_h);
    cudaGetSymbolAddress((void**)&nagg, g_nagg);
    cudaGetSymbolAddress((void**)&naggH, g_naggH);
    cudaGetSymbolAddress((void**)&eemb, g_eemb);
    cudaGetSymbolAddress((void**)&means, g_means);
    cudaGetSymbolAddress((void**)&cnt,   g_cnt);
    cudaGetSymbolAddress((void**)&deg,   g_deg);
    cudaGetSymbolAddress((void**)&degmax, g_degmax);

    const int SMEM128 = (128 * 64 + 128 * 132) * 4;  // 100352
    const int SMEM64  = (64 * 64 + 128 * 68) * 4;    // 51200
    cudaFuncSetAttribute(k_layer2<false>, cudaFuncAttributeMaxDynamicSharedMemorySize, SMEM128);
    cudaFuncSetAttribute(k_layer2<true>,  cudaFuncAttributeMaxDynamicSharedMemorySize, SMEM128);
    cudaFuncSetAttribute(k_gemm64, cudaFuncAttributeMaxDynamicSharedMemorySize, SMEM64);

    int gFI = (E + n * 64 + 255) / 256;
    int gHW = (n * 16 + 255) / 256;
    int gG  = (n + 127) / 128;
    int gA  = (n + 255) / 256;

    cudaMemsetAsync(deg,    0, (size_t)n * sizeof(int));
    cudaMemsetAsync(degmax, 0, sizeof(int));
    cudaMemsetAsync(means,  0, (size_t)MAXG * FD * sizeof(float));
    cudaMemsetAsync(cnt,    0, (size_t)MAXG * sizeof(float));

    k_fillpad<<<gFI, 256>>>(row, col, x, Wi, We1, E, n, nobs);   // kernel 1
    k_dgather<<<gHW, 256>>>(hbuf, curA, naggH, nagg, n);         // kernel 2
    k_gemm64<<<gG, 128, SMEM64>>>(naggH, We2, eemb, n);          // kernel 3

    float* cin = curA;
    float* cout = curB;
    for (int l = 0; l < L; l++) {
        bool last = (l == L - 1);
        if (l > 0) k_gather<<<gHW, 256>>>(cin, nagg, n);
        if (!last) {
            k_layer2<false><<<gG, 128, SMEM128>>>(nagg, eemb, cin,        // kernel 4 (l=0): profiled
                                                  Wmsg + (size_t)l * 8192,
                                                  Wupd + (size_t)l * 8192,
                                                  cout, nullptr, nullptr, nullptr, n);
            float* tmp = cin; cin = cout; cout = tmp;
        } else {
            k_layer2<true><<<gG, 128, SMEM128>>>(nagg, eemb, cin,
                                                 Wmsg + (size_t)l * 8192,
                                                 Wupd + (size_t)l * 8192,
                                                 nullptr, Wr, batch, out, n);
        }
    }

    k_gconst<<<MAXG, 64>>>(Wp, Wr, br);
    k_addg<<<gA, 256>>>(batch, out, n);
}